// round 1
// baseline (speedup 1.0000x reference)
#include <cuda_runtime.h>
#include <math.h>

#define NTOK   2048
#define DMODEL 256
#define DFF    1024
#define NHEAD  8
#define DHEAD  32
#define KWIN   5
#define NNBR   125   // 5*5*5

// ---------------- scratch (device globals; no allocations allowed) ----------
__device__ float g_n1[NTOK * DMODEL];
__device__ float g_q [NTOK * DMODEL];
__device__ float g_k [NTOK * DMODEL];
__device__ float g_v [NTOK * DMODEL];
__device__ float g_at[NTOK * DMODEL];
__device__ float g_h [NTOK * DMODEL];
__device__ float g_y [NTOK * DMODEL];
__device__ float g_fa[NTOK * DFF];
__device__ float g_fb[NTOK * DFF];

// ---------------- RMSNorm: one block per token, 256 threads -----------------
__global__ void rmsnorm_k(const float* __restrict__ x, const float* __restrict__ w,
                          float* __restrict__ y) {
    const int token = blockIdx.x;
    const int tid   = threadIdx.x;
    const float v   = x[token * DMODEL + tid];
    float s = v * v;
    #pragma unroll
    for (int o = 16; o; o >>= 1) s += __shfl_xor_sync(0xffffffffu, s, o);
    __shared__ float ws[8];
    if ((tid & 31) == 0) ws[tid >> 5] = s;
    __syncthreads();
    float tot = 0.f;
    #pragma unroll
    for (int i = 0; i < 8; i++) tot += ws[i];
    const float scale = rsqrtf(tot * (1.0f / DMODEL) + 1e-6f);
    y[token * DMODEL + tid] = v * scale * w[tid];
}

// ---------------- GEMM: C[M,N] = A[M,K] @ B[K,N] (+bias) (+res) -------------
// BM=BN=64, BK=16, 256 threads, 4x4 micro-tile per thread. All dims are
// multiples of the tile sizes in this problem, so no bounds checks.
__global__ __launch_bounds__(256) void gemm_k(
    const float* __restrict__ A, const float* __restrict__ B,
    const float* __restrict__ bias, const float* __restrict__ res,
    float* __restrict__ C, int M, int N, int Kd) {

    __shared__ float As[16][64];
    __shared__ float Bs[16][64];

    const int tid = threadIdx.x;
    const int bm  = blockIdx.y * 64;
    const int bn  = blockIdx.x * 64;
    const int ty  = tid >> 4;   // 0..15
    const int tx  = tid & 15;   // 0..15

    const int aRow = tid >> 2;          // 0..63
    const int aK4  = (tid & 3) * 4;     // 0,4,8,12
    const int bRow = tid >> 4;          // 0..15
    const int bC4  = (tid & 15) * 4;    // 0..60

    float acc[4][4];
    #pragma unroll
    for (int i = 0; i < 4; i++)
        #pragma unroll
        for (int j = 0; j < 4; j++) acc[i][j] = 0.f;

    for (int k0 = 0; k0 < Kd; k0 += 16) {
        // load A tile (transposed into As[k][m])
        const float4 a4 = *(const float4*)&A[(size_t)(bm + aRow) * Kd + k0 + aK4];
        As[aK4 + 0][aRow] = a4.x;
        As[aK4 + 1][aRow] = a4.y;
        As[aK4 + 2][aRow] = a4.z;
        As[aK4 + 3][aRow] = a4.w;
        // load B tile
        const float4 b4 = *(const float4*)&B[(size_t)(k0 + bRow) * N + bn + bC4];
        *(float4*)&Bs[bRow][bC4] = b4;
        __syncthreads();

        #pragma unroll
        for (int kk = 0; kk < 16; kk++) {
            const float4 av = *(const float4*)&As[kk][ty * 4];
            const float4 bv = *(const float4*)&Bs[kk][tx * 4];
            const float ar[4] = {av.x, av.y, av.z, av.w};
            const float br[4] = {bv.x, bv.y, bv.z, bv.w};
            #pragma unroll
            for (int i = 0; i < 4; i++)
                #pragma unroll
                for (int j = 0; j < 4; j++)
                    acc[i][j] = fmaf(ar[i], br[j], acc[i][j]);
        }
        __syncthreads();
    }

    // epilogue
    const int col = bn + tx * 4;
    float4 bi = make_float4(0.f, 0.f, 0.f, 0.f);
    if (bias) bi = *(const float4*)&bias[col];
    #pragma unroll
    for (int i = 0; i < 4; i++) {
        const int row = bm + ty * 4 + i;
        float4 o;
        o.x = acc[i][0] + bi.x;
        o.y = acc[i][1] + bi.y;
        o.z = acc[i][2] + bi.z;
        o.w = acc[i][3] + bi.w;
        if (res) {
            const float4 r = *(const float4*)&res[(size_t)row * N + col];
            o.x += r.x; o.y += r.y; o.z += r.z; o.w += r.w;
        }
        *(float4*)&C[(size_t)row * N + col] = o;
    }
}

// ---------------- NA3D attention: one block per token, warp per head --------
__global__ __launch_bounds__(256) void na3d_k(
    const float* __restrict__ q, const float* __restrict__ k,
    const float* __restrict__ v, float* __restrict__ out) {

    const int token = blockIdx.x;
    const int w = token & 15;
    const int h = (token >> 4) & 15;
    const int t = token >> 8;
    const int tid  = threadIdx.x;
    const int head = tid >> 5;
    const int lane = tid & 31;

    __shared__ int   nidx[NNBR];
    __shared__ float qs[DMODEL];
    __shared__ float probs[NHEAD][128];

    qs[tid] = q[(size_t)token * DMODEL + tid];
    if (tid < NNBR) {
        const int mt = tid / 25;
        const int mh = (tid / 5) % 5;
        const int mw = tid % 5;
        int tn = t - (KWIN - 1) + mt;          // causal in T
        const bool valid = (tn >= 0);
        if (tn < 0) tn = 0;
        const int hs = min(max(h - 2, 0), 11); // non-causal clipped window
        const int ws = min(max(w - 2, 0), 11);
        const int ni = ((tn * 16) + (hs + mh)) * 16 + (ws + mw);
        nidx[tid] = valid ? ni : -1;
    }
    __syncthreads();

    const float qv = qs[head * DHEAD + lane];
    const float scale = 0.17677669529663687f;  // 1/sqrt(32)

    // logits
    for (int m = 0; m < NNBR; m++) {
        const int ni = nidx[m];
        float p = 0.f;
        if (ni >= 0) p = qv * k[(size_t)ni * DMODEL + head * DHEAD + lane];
        #pragma unroll
        for (int o = 16; o; o >>= 1) p += __shfl_xor_sync(0xffffffffu, p, o);
        if (lane == 0) probs[head][m] = (ni >= 0) ? p * scale : -INFINITY;
    }
    __syncwarp();

    // softmax (within warp)
    float mmax = -INFINITY;
    for (int m = lane; m < NNBR; m += 32) mmax = fmaxf(mmax, probs[head][m]);
    #pragma unroll
    for (int o = 16; o; o >>= 1) mmax = fmaxf(mmax, __shfl_xor_sync(0xffffffffu, mmax, o));
    float ssum = 0.f;
    for (int m = lane; m < NNBR; m += 32) {
        const float e = __expf(probs[head][m] - mmax);
        probs[head][m] = e;
        ssum += e;
    }
    #pragma unroll
    for (int o = 16; o; o >>= 1) ssum += __shfl_xor_sync(0xffffffffu, ssum, o);
    const float inv = 1.f / ssum;
    __syncwarp();

    // output: lane = channel within head
    float acc = 0.f;
    for (int m = 0; m < NNBR; m++) {
        const int ni = nidx[m];
        if (ni >= 0)
            acc = fmaf(probs[head][m], v[(size_t)ni * DMODEL + head * DHEAD + lane], acc);
    }
    out[(size_t)token * DMODEL + head * DHEAD + lane] = acc * inv;
}

// ---------------- SiLU(a) * b, in-place into a -------------------------------
__global__ void silu_mul_k(float* __restrict__ a, const float* __restrict__ b, int n) {
    const int i = blockIdx.x * blockDim.x + threadIdx.x;
    if (i < n) {
        const float av = a[i];
        a[i] = av / (1.f + __expf(-av)) * b[i];
    }
}

// ---------------- launch ------------------------------------------------------
extern "C" void kernel_launch(void* const* d_in, const int* in_sizes, int n_in,
                              void* d_out, int out_size) {
    const float* x   = (const float*)d_in[0];
    const float* n1w = (const float*)d_in[1];
    const float* n2w = (const float*)d_in[2];
    const float* wq  = (const float*)d_in[3];
    const float* bq  = (const float*)d_in[4];
    const float* wk  = (const float*)d_in[5];
    const float* bk  = (const float*)d_in[6];
    const float* wv  = (const float*)d_in[7];
    const float* bv  = (const float*)d_in[8];
    const float* wo  = (const float*)d_in[9];
    const float* bo  = (const float*)d_in[10];
    const float* w1  = (const float*)d_in[11];
    const float* w2  = (const float*)d_in[12];
    const float* w3  = (const float*)d_in[13];
    float* out = (float*)d_out;

    float *p_n1, *p_q, *p_k, *p_v, *p_at, *p_h, *p_y, *p_fa, *p_fb;
    cudaGetSymbolAddress((void**)&p_n1, g_n1);
    cudaGetSymbolAddress((void**)&p_q,  g_q);
    cudaGetSymbolAddress((void**)&p_k,  g_k);
    cudaGetSymbolAddress((void**)&p_v,  g_v);
    cudaGetSymbolAddress((void**)&p_at, g_at);
    cudaGetSymbolAddress((void**)&p_h,  g_h);
    cudaGetSymbolAddress((void**)&p_y,  g_y);
    cudaGetSymbolAddress((void**)&p_fa, g_fa);
    cudaGetSymbolAddress((void**)&p_fb, g_fb);

    const dim3 blk(256);
    const dim3 gD (DMODEL / 64, NTOK / 64);   // N=256 outputs
    const dim3 gF (DFF / 64,    NTOK / 64);   // N=1024 outputs

    // 1) n1 = rmsnorm(x, norm1_w)
    rmsnorm_k<<<NTOK, DMODEL>>>(x, n1w, p_n1);
    // 2) q,k,v = n1 @ {wq,wk,wv} + bias
    gemm_k<<<gD, blk>>>(p_n1, wq, bq, nullptr, p_q, NTOK, DMODEL, DMODEL);
    gemm_k<<<gD, blk>>>(p_n1, wk, bk, nullptr, p_k, NTOK, DMODEL, DMODEL);
    gemm_k<<<gD, blk>>>(p_n1, wv, bv, nullptr, p_v, NTOK, DMODEL, DMODEL);
    // 3) neighborhood attention
    na3d_k<<<NTOK, 256>>>(p_q, p_k, p_v, p_at);
    // 4) h = x + attn @ wo + bo
    gemm_k<<<gD, blk>>>(p_at, wo, bo, x, p_h, NTOK, DMODEL, DMODEL);
    // 5) y = rmsnorm(h, norm2_w)
    rmsnorm_k<<<NTOK, DMODEL>>>(p_h, n2w, p_y);
    // 6) fa = y@w1 ; fb = y@w2
    gemm_k<<<gF, blk>>>(p_y, w1, nullptr, nullptr, p_fa, NTOK, DFF, DMODEL);
    gemm_k<<<gF, blk>>>(p_y, w2, nullptr, nullptr, p_fb, NTOK, DFF, DMODEL);
    // 7) fa = silu(fa) * fb
    silu_mul_k<<<(NTOK * DFF) / 256, 256>>>(p_fa, p_fb, NTOK * DFF);
    // 8) out = h + fa @ w3
    gemm_k<<<gD, blk>>>(p_fa, w3, nullptr, p_h, out, NTOK, DMODEL, DFF);
}

// round 2
// speedup vs baseline: 1.6467x; 1.6467x over previous
#include <cuda_runtime.h>
#include <math.h>
#include <stdint.h>

#define NTOK   2048
#define DMODEL 256
#define DFF    1024
#define NHEAD  8
#define DHEAD  32
#define KWIN   5
#define NNBR   125   // 5*5*5

// ---------------- scratch (device globals; no allocations allowed) ----------
__device__ float g_n1[NTOK * DMODEL];
__device__ float g_q [NTOK * DMODEL];
__device__ float g_k [NTOK * DMODEL];
__device__ float g_v [NTOK * DMODEL];
__device__ float g_at[NTOK * DMODEL];
__device__ float g_h [NTOK * DMODEL];
__device__ float g_y [NTOK * DMODEL];
__device__ float g_fa[NTOK * DFF];

// ---------------- helpers ----------------------------------------------------
__device__ __forceinline__ uint32_t f2tf(float f) {
    uint32_t u;
    asm("cvt.rna.tf32.f32 %0, %1;" : "=r"(u) : "f"(f));
    return u;
}

__device__ __forceinline__ void mma_tf32(float d[4], const uint32_t a[4], const uint32_t b[2]) {
    asm volatile(
        "mma.sync.aligned.m16n8k8.row.col.f32.tf32.tf32.f32 "
        "{%0,%1,%2,%3},{%4,%5,%6,%7},{%8,%9},{%0,%1,%2,%3};"
        : "+f"(d[0]), "+f"(d[1]), "+f"(d[2]), "+f"(d[3])
        : "r"(a[0]), "r"(a[1]), "r"(a[2]), "r"(a[3]), "r"(b[0]), "r"(b[1]));
}

// A-tile smem: [64 rows][36 words] (stride-36 pad => conflict-free frag loads)
// B-tile smem: [32 rows][72 words] (stride-72 pad => conflict-free frag loads)
#define AS_STRIDE 36
#define BS_STRIDE 72

// ---------------- RMSNorm: one block per token, 256 threads -----------------
__global__ void rmsnorm_k(const float* __restrict__ x, const float* __restrict__ w,
                          float* __restrict__ y) {
    const int token = blockIdx.x;
    const int tid   = threadIdx.x;
    const float v   = x[token * DMODEL + tid];
    float s = v * v;
    #pragma unroll
    for (int o = 16; o; o >>= 1) s += __shfl_xor_sync(0xffffffffu, s, o);
    __shared__ float ws[8];
    if ((tid & 31) == 0) ws[tid >> 5] = s;
    __syncthreads();
    float tot = 0.f;
    #pragma unroll
    for (int i = 0; i < 8; i++) tot += ws[i];
    const float scale = rsqrtf(tot * (1.0f / DMODEL) + 1e-6f);
    y[token * DMODEL + tid] = v * scale * w[tid];
}

// ---------------- TF32 tensor-core GEMM --------------------------------------
// C[M,N] = A[M,K] @ B[K,N] (+bias) (+res). BM=BN=64, BK=32, 128 threads,
// 4 warps in 2x2, each warp a 32x32 tile (2 m16 x 4 n8 mma fragments).
// blockIdx.z selects among up to 3 (B, bias, C) triples (QKV fusion).
__global__ __launch_bounds__(128) void gemm_tf32_k(
    const float* __restrict__ A,
    const float* __restrict__ B0, const float* __restrict__ B1, const float* __restrict__ B2,
    const float* __restrict__ bias0, const float* __restrict__ bias1, const float* __restrict__ bias2,
    const float* __restrict__ res,
    float* __restrict__ C0, float* __restrict__ C1, float* __restrict__ C2,
    int N, int K) {

    const int z = blockIdx.z;
    const float* B    = (z == 0) ? B0    : (z == 1) ? B1    : B2;
    const float* bias = (z == 0) ? bias0 : (z == 1) ? bias1 : bias2;
    float*       C    = (z == 0) ? C0    : (z == 1) ? C1    : C2;

    __shared__ uint32_t As[64 * AS_STRIDE];
    __shared__ uint32_t Bs[32 * BS_STRIDE];

    const int tid  = threadIdx.x;
    const int warp = tid >> 5;
    const int lane = tid & 31;
    const int g    = lane >> 2;
    const int tig  = lane & 3;
    const int warpRow = (warp & 1) * 32;
    const int warpCol = (warp >> 1) * 32;
    const int bm = blockIdx.y * 64;
    const int bn = blockIdx.x * 64;

    float acc[2][4][4];
    #pragma unroll
    for (int mt = 0; mt < 2; mt++)
        #pragma unroll
        for (int nt = 0; nt < 4; nt++)
            #pragma unroll
            for (int i = 0; i < 4; i++) acc[mt][nt][i] = 0.f;

    const int aRow0 = tid >> 3;          // 0..15
    const int aCol  = (tid & 7) * 4;     // 0..28
    const int bRow0 = tid >> 4;          // 0..7
    const int bCol  = (tid & 15) * 4;    // 0..60

    for (int k0 = 0; k0 < K; k0 += 32) {
        #pragma unroll
        for (int i = 0; i < 4; i++) {
            const int r = aRow0 + i * 16;
            const float4 v = *(const float4*)&A[(size_t)(bm + r) * K + k0 + aCol];
            uint4 u;
            u.x = f2tf(v.x); u.y = f2tf(v.y); u.z = f2tf(v.z); u.w = f2tf(v.w);
            *(uint4*)&As[r * AS_STRIDE + aCol] = u;
        }
        #pragma unroll
        for (int i = 0; i < 4; i++) {
            const int r = bRow0 + i * 8;
            const float4 v = *(const float4*)&B[(size_t)(k0 + r) * N + bn + bCol];
            uint4 u;
            u.x = f2tf(v.x); u.y = f2tf(v.y); u.z = f2tf(v.z); u.w = f2tf(v.w);
            *(uint4*)&Bs[r * BS_STRIDE + bCol] = u;
        }
        __syncthreads();

        #pragma unroll
        for (int s = 0; s < 4; s++) {
            uint32_t a[2][4], b[4][2];
            #pragma unroll
            for (int mt = 0; mt < 2; mt++) {
                const int r0 = warpRow + mt * 16 + g;
                a[mt][0] = As[r0 * AS_STRIDE + 8 * s + tig];
                a[mt][1] = As[(r0 + 8) * AS_STRIDE + 8 * s + tig];
                a[mt][2] = As[r0 * AS_STRIDE + 8 * s + 4 + tig];
                a[mt][3] = As[(r0 + 8) * AS_STRIDE + 8 * s + 4 + tig];
            }
            #pragma unroll
            for (int nt = 0; nt < 4; nt++) {
                const int c = warpCol + nt * 8 + g;
                b[nt][0] = Bs[(8 * s + tig) * BS_STRIDE + c];
                b[nt][1] = Bs[(8 * s + 4 + tig) * BS_STRIDE + c];
            }
            #pragma unroll
            for (int mt = 0; mt < 2; mt++)
                #pragma unroll
                for (int nt = 0; nt < 4; nt++)
                    mma_tf32(acc[mt][nt], a[mt], b[nt]);
        }
        __syncthreads();
    }

    // epilogue
    #pragma unroll
    for (int mt = 0; mt < 2; mt++) {
        #pragma unroll
        for (int nt = 0; nt < 4; nt++) {
            const int row0 = bm + warpRow + mt * 16 + g;
            const int col  = bn + warpCol + nt * 8 + 2 * tig;
            float b0 = 0.f, b1 = 0.f;
            if (bias) { b0 = bias[col]; b1 = bias[col + 1]; }
            float2 o0 = make_float2(acc[mt][nt][0] + b0, acc[mt][nt][1] + b1);
            float2 o1 = make_float2(acc[mt][nt][2] + b0, acc[mt][nt][3] + b1);
            if (res) {
                const float2 r0 = *(const float2*)&res[(size_t)row0 * N + col];
                const float2 r1 = *(const float2*)&res[(size_t)(row0 + 8) * N + col];
                o0.x += r0.x; o0.y += r0.y;
                o1.x += r1.x; o1.y += r1.y;
            }
            *(float2*)&C[(size_t)row0 * N + col]       = o0;
            *(float2*)&C[(size_t)(row0 + 8) * N + col] = o1;
        }
    }
}

// ---------------- fused gate GEMM: silu(A@W1) * (A@W2) -----------------------
__global__ __launch_bounds__(128) void gemm_gate_k(
    const float* __restrict__ A, const float* __restrict__ W1, const float* __restrict__ W2,
    float* __restrict__ C, int N, int K) {

    __shared__ uint32_t As[64 * AS_STRIDE];
    __shared__ uint32_t B1s[32 * BS_STRIDE];
    __shared__ uint32_t B2s[32 * BS_STRIDE];

    const int tid  = threadIdx.x;
    const int warp = tid >> 5;
    const int lane = tid & 31;
    const int g    = lane >> 2;
    const int tig  = lane & 3;
    const int warpRow = (warp & 1) * 32;
    const int warpCol = (warp >> 1) * 32;
    const int bm = blockIdx.y * 64;
    const int bn = blockIdx.x * 64;

    float acc1[2][4][4], acc2[2][4][4];
    #pragma unroll
    for (int mt = 0; mt < 2; mt++)
        #pragma unroll
        for (int nt = 0; nt < 4; nt++)
            #pragma unroll
            for (int i = 0; i < 4; i++) { acc1[mt][nt][i] = 0.f; acc2[mt][nt][i] = 0.f; }

    const int aRow0 = tid >> 3;
    const int aCol  = (tid & 7) * 4;
    const int bRow0 = tid >> 4;
    const int bCol  = (tid & 15) * 4;

    for (int k0 = 0; k0 < K; k0 += 32) {
        #pragma unroll
        for (int i = 0; i < 4; i++) {
            const int r = aRow0 + i * 16;
            const float4 v = *(const float4*)&A[(size_t)(bm + r) * K + k0 + aCol];
            uint4 u;
            u.x = f2tf(v.x); u.y = f2tf(v.y); u.z = f2tf(v.z); u.w = f2tf(v.w);
            *(uint4*)&As[r * AS_STRIDE + aCol] = u;
        }
        #pragma unroll
        for (int i = 0; i < 4; i++) {
            const int r = bRow0 + i * 8;
            const size_t off = (size_t)(k0 + r) * N + bn + bCol;
            const float4 v1 = *(const float4*)&W1[off];
            const float4 v2 = *(const float4*)&W2[off];
            uint4 u1, u2;
            u1.x = f2tf(v1.x); u1.y = f2tf(v1.y); u1.z = f2tf(v1.z); u1.w = f2tf(v1.w);
            u2.x = f2tf(v2.x); u2.y = f2tf(v2.y); u2.z = f2tf(v2.z); u2.w = f2tf(v2.w);
            *(uint4*)&B1s[r * BS_STRIDE + bCol] = u1;
            *(uint4*)&B2s[r * BS_STRIDE + bCol] = u2;
        }
        __syncthreads();

        #pragma unroll
        for (int s = 0; s < 4; s++) {
            uint32_t a[2][4], b1[4][2], b2[4][2];
            #pragma unroll
            for (int mt = 0; mt < 2; mt++) {
                const int r0 = warpRow + mt * 16 + g;
                a[mt][0] = As[r0 * AS_STRIDE + 8 * s + tig];
                a[mt][1] = As[(r0 + 8) * AS_STRIDE + 8 * s + tig];
                a[mt][2] = As[r0 * AS_STRIDE + 8 * s + 4 + tig];
                a[mt][3] = As[(r0 + 8) * AS_STRIDE + 8 * s + 4 + tig];
            }
            #pragma unroll
            for (int nt = 0; nt < 4; nt++) {
                const int c = warpCol + nt * 8 + g;
                b1[nt][0] = B1s[(8 * s + tig) * BS_STRIDE + c];
                b1[nt][1] = B1s[(8 * s + 4 + tig) * BS_STRIDE + c];
                b2[nt][0] = B2s[(8 * s + tig) * BS_STRIDE + c];
                b2[nt][1] = B2s[(8 * s + 4 + tig) * BS_STRIDE + c];
            }
            #pragma unroll
            for (int mt = 0; mt < 2; mt++)
                #pragma unroll
                for (int nt = 0; nt < 4; nt++) {
                    mma_tf32(acc1[mt][nt], a[mt], b1[nt]);
                    mma_tf32(acc2[mt][nt], a[mt], b2[nt]);
                }
        }
        __syncthreads();
    }

    #pragma unroll
    for (int mt = 0; mt < 2; mt++) {
        #pragma unroll
        for (int nt = 0; nt < 4; nt++) {
            const int row0 = bm + warpRow + mt * 16 + g;
            const int col  = bn + warpCol + nt * 8 + 2 * tig;
            #pragma unroll
            for (int half = 0; half < 2; half++) {
                const int row = row0 + half * 8;
                const float a0 = acc1[mt][nt][half * 2 + 0];
                const float a1 = acc1[mt][nt][half * 2 + 1];
                float2 o;
                o.x = a0 / (1.f + __expf(-a0)) * acc2[mt][nt][half * 2 + 0];
                o.y = a1 / (1.f + __expf(-a1)) * acc2[mt][nt][half * 2 + 1];
                *(float2*)&C[(size_t)row * N + col] = o;
            }
        }
    }
}

// ---------------- NA3D attention: one block per token, warp per head --------
__global__ __launch_bounds__(256) void na3d_k(
    const float* __restrict__ q, const float* __restrict__ k,
    const float* __restrict__ v, float* __restrict__ out) {

    const int token = blockIdx.x;
    const int w = token & 15;
    const int h = (token >> 4) & 15;
    const int t = token >> 8;
    const int tid  = threadIdx.x;
    const int head = tid >> 5;
    const int lane = tid & 31;

    __shared__ int   nidx[NNBR];
    __shared__ float qs[DMODEL];
    __shared__ float probs[NHEAD][128];

    qs[tid] = q[(size_t)token * DMODEL + tid];
    if (tid < NNBR) {
        const int mt = tid / 25;
        const int mh = (tid / 5) % 5;
        const int mw = tid % 5;
        int tn = t - (KWIN - 1) + mt;          // causal in T
        const bool valid = (tn >= 0);
        if (tn < 0) tn = 0;
        const int hs = min(max(h - 2, 0), 11); // non-causal clipped window
        const int ws = min(max(w - 2, 0), 11);
        const int ni = ((tn * 16) + (hs + mh)) * 16 + (ws + mw);
        nidx[tid] = valid ? ni : -1;
    }
    __syncthreads();

    const float qv = qs[head * DHEAD + lane];
    const float scale = 0.17677669529663687f;  // 1/sqrt(32)

    for (int m = 0; m < NNBR; m++) {
        const int ni = nidx[m];
        float p = 0.f;
        if (ni >= 0) p = qv * k[(size_t)ni * DMODEL + head * DHEAD + lane];
        #pragma unroll
        for (int o = 16; o; o >>= 1) p += __shfl_xor_sync(0xffffffffu, p, o);
        if (lane == 0) probs[head][m] = (ni >= 0) ? p * scale : -INFINITY;
    }
    __syncwarp();

    float mmax = -INFINITY;
    for (int m = lane; m < NNBR; m += 32) mmax = fmaxf(mmax, probs[head][m]);
    #pragma unroll
    for (int o = 16; o; o >>= 1) mmax = fmaxf(mmax, __shfl_xor_sync(0xffffffffu, mmax, o));
    float ssum = 0.f;
    for (int m = lane; m < NNBR; m += 32) {
        const float e = __expf(probs[head][m] - mmax);
        probs[head][m] = e;
        ssum += e;
    }
    #pragma unroll
    for (int o = 16; o; o >>= 1) ssum += __shfl_xor_sync(0xffffffffu, ssum, o);
    const float inv = 1.f / ssum;
    __syncwarp();

    float acc = 0.f;
    for (int m = 0; m < NNBR; m++) {
        const int ni = nidx[m];
        if (ni >= 0)
            acc = fmaf(probs[head][m], v[(size_t)ni * DMODEL + head * DHEAD + lane], acc);
    }
    out[(size_t)token * DMODEL + head * DHEAD + lane] = acc * inv;
}

// ---------------- launch ------------------------------------------------------
extern "C" void kernel_launch(void* const* d_in, const int* in_sizes, int n_in,
                              void* d_out, int out_size) {
    const float* x   = (const float*)d_in[0];
    const float* n1w = (const float*)d_in[1];
    const float* n2w = (const float*)d_in[2];
    const float* wq  = (const float*)d_in[3];
    const float* bq  = (const float*)d_in[4];
    const float* wk  = (const float*)d_in[5];
    const float* bk  = (const float*)d_in[6];
    const float* wv  = (const float*)d_in[7];
    const float* bv  = (const float*)d_in[8];
    const float* wo  = (const float*)d_in[9];
    const float* bo  = (const float*)d_in[10];
    const float* w1  = (const float*)d_in[11];
    const float* w2  = (const float*)d_in[12];
    const float* w3  = (const float*)d_in[13];
    float* out = (float*)d_out;

    float *p_n1, *p_q, *p_k, *p_v, *p_at, *p_h, *p_y, *p_fa;
    cudaGetSymbolAddress((void**)&p_n1, g_n1);
    cudaGetSymbolAddress((void**)&p_q,  g_q);
    cudaGetSymbolAddress((void**)&p_k,  g_k);
    cudaGetSymbolAddress((void**)&p_v,  g_v);
    cudaGetSymbolAddress((void**)&p_at, g_at);
    cudaGetSymbolAddress((void**)&p_h,  g_h);
    cudaGetSymbolAddress((void**)&p_y,  g_y);
    cudaGetSymbolAddress((void**)&p_fa, g_fa);

    const dim3 blk(128);

    // 1) n1 = rmsnorm(x, norm1_w)
    rmsnorm_k<<<NTOK, DMODEL>>>(x, n1w, p_n1);

    // 2) q,k,v = n1 @ {wq,wk,wv} + bias   (fused via grid.z)
    gemm_tf32_k<<<dim3(DMODEL / 64, NTOK / 64, 3), blk>>>(
        p_n1, wq, wk, wv, bq, bk, bv, nullptr, p_q, p_k, p_v, DMODEL, DMODEL);

    // 3) neighborhood attention
    na3d_k<<<NTOK, 256>>>(p_q, p_k, p_v, p_at);

    // 4) h = x + attn @ wo + bo
    gemm_tf32_k<<<dim3(DMODEL / 64, NTOK / 64, 1), blk>>>(
        p_at, wo, nullptr, nullptr, bo, nullptr, nullptr, x, p_h, nullptr, nullptr,
        DMODEL, DMODEL);

    // 5) y = rmsnorm(h, norm2_w)
    rmsnorm_k<<<NTOK, DMODEL>>>(p_h, n2w, p_y);

    // 6) fa = silu(y@w1) * (y@w2)   (fused dual-B GEMM)
    gemm_gate_k<<<dim3(DFF / 64, NTOK / 64, 1), blk>>>(p_y, w1, w2, p_fa, DFF, DMODEL);

    // 7) out = h + fa @ w3
    gemm_tf32_k<<<dim3(DMODEL / 64, NTOK / 64, 1), blk>>>(
        p_fa, w3, nullptr, nullptr, nullptr, nullptr, nullptr, p_h, out, nullptr, nullptr,
        DMODEL, DFF);
}

// round 3
// speedup vs baseline: 2.6335x; 1.5993x over previous
#include <cuda_runtime.h>
#include <math.h>
#include <stdint.h>

#define NTOK   2048
#define DMODEL 256
#define DFF    1024
#define NHEAD  8
#define DHEAD  32
#define KWIN   5
#define NNBR   125   // 5*5*5

// ---------------- scratch (device globals; no allocations allowed) ----------
__device__ float g_n1[NTOK * DMODEL];
__device__ float g_q [NTOK * DMODEL];
__device__ float g_k [NTOK * DMODEL];
__device__ float g_v [NTOK * DMODEL];
__device__ float g_at[NTOK * DMODEL];
__device__ float g_h [NTOK * DMODEL];
__device__ float g_y [NTOK * DMODEL];
__device__ float g_fa[NTOK * DFF];

// ---------------- helpers ----------------------------------------------------
__device__ __forceinline__ void mma_tf32(float d[4], const uint32_t a[4], const uint32_t b[2]) {
    asm volatile(
        "mma.sync.aligned.m16n8k8.row.col.f32.tf32.tf32.f32 "
        "{%0,%1,%2,%3},{%4,%5,%6,%7},{%8,%9},{%0,%1,%2,%3};"
        : "+f"(d[0]), "+f"(d[1]), "+f"(d[2]), "+f"(d[3])
        : "r"(a[0]), "r"(a[1]), "r"(a[2]), "r"(a[3]), "r"(b[0]), "r"(b[1]));
}

__device__ __forceinline__ void cp_async16(void* smem_dst, const void* gsrc) {
    uint32_t s = (uint32_t)__cvta_generic_to_shared(smem_dst);
    asm volatile("cp.async.cg.shared.global [%0], [%1], 16;" :: "r"(s), "l"(gsrc));
}
__device__ __forceinline__ void cp_commit() { asm volatile("cp.async.commit_group;"); }

#define ASTR 36   // A smem stride (words per m-row): banks = 4g+tig, conflict-free
#define BSTR 68   // B smem stride (words per k-row): banks = 4tig+g, conflict-free

// ---------------- RMSNorm: one block per token, 256 threads -----------------
__global__ void rmsnorm_k(const float* __restrict__ x, const float* __restrict__ w,
                          float* __restrict__ y) {
    const int token = blockIdx.x;
    const int tid   = threadIdx.x;
    const float v   = x[token * DMODEL + tid];
    float s = v * v;
    #pragma unroll
    for (int o = 16; o; o >>= 1) s += __shfl_xor_sync(0xffffffffu, s, o);
    __shared__ float ws[8];
    if ((tid & 31) == 0) ws[tid >> 5] = s;
    __syncthreads();
    float tot = 0.f;
    #pragma unroll
    for (int i = 0; i < 8; i++) tot += ws[i];
    const float scale = rsqrtf(tot * (1.0f / DMODEL) + 1e-6f);
    y[token * DMODEL + tid] = v * scale * w[tid];
}

// ---------------- TF32 GEMM v2: 64x64x32 tiles, 256 thr, cp.async dbl-buf ----
// blockIdx.z selects among up to 3 (B, bias, C) triples (QKV fusion).
__global__ __launch_bounds__(256) void gemm_tf32_k(
    const float* __restrict__ A,
    const float* __restrict__ B0, const float* __restrict__ B1, const float* __restrict__ B2,
    const float* __restrict__ bias0, const float* __restrict__ bias1, const float* __restrict__ bias2,
    const float* __restrict__ res,
    float* __restrict__ C0, float* __restrict__ C1, float* __restrict__ C2,
    int N, int K) {

    const int z = blockIdx.z;
    const float* B    = (z == 0) ? B0    : (z == 1) ? B1    : B2;
    const float* bias = (z == 0) ? bias0 : (z == 1) ? bias1 : bias2;
    float*       C    = (z == 0) ? C0    : (z == 1) ? C1    : C2;

    __shared__ float As[2][64 * ASTR];
    __shared__ float Bs[2][32 * BSTR];

    const int tid  = threadIdx.x;
    const int warp = tid >> 5;
    const int lane = tid & 31;
    const int g    = lane >> 2;
    const int tig  = lane & 3;
    const int warpRow = (warp & 3) * 16;   // 4 warp-rows
    const int warpCol = (warp >> 2) * 32;  // 2 warp-cols
    const int bm = blockIdx.y * 64;
    const int bn = blockIdx.x * 64;

    float acc[4][4];
    #pragma unroll
    for (int nt = 0; nt < 4; nt++)
        #pragma unroll
        for (int i = 0; i < 4; i++) acc[nt][i] = 0.f;

    const int nkt = K >> 5;

    auto load_tile = [&](int buf, int k0) {
        #pragma unroll
        for (int j = 0; j < 2; j++) {          // A: 512 chunks
            const int c = tid + 256 * j;
            const int row = c >> 3, kc = (c & 7) * 4;
            cp_async16(&As[buf][row * ASTR + kc], &A[(size_t)(bm + row) * K + k0 + kc]);
        }
        #pragma unroll
        for (int j = 0; j < 2; j++) {          // B: 512 chunks
            const int c = tid + 256 * j;
            const int row = c >> 4, nc = (c & 15) * 4;
            cp_async16(&Bs[buf][row * BSTR + nc], &B[(size_t)(k0 + row) * N + bn + nc]);
        }
        cp_commit();
    };

    load_tile(0, 0);

    for (int kt = 0; kt < nkt; kt++) {
        const int buf = kt & 1;
        if (kt + 1 < nkt) load_tile(buf ^ 1, (kt + 1) * 32);
        if (kt + 1 < nkt) asm volatile("cp.async.wait_group 1;");
        else              asm volatile("cp.async.wait_group 0;");
        __syncthreads();

        #pragma unroll
        for (int s = 0; s < 4; s++) {
            uint32_t a[4], b[4][2];
            const int r0 = warpRow + g;
            a[0] = __float_as_uint(As[buf][r0 * ASTR + 8 * s + tig]);
            a[1] = __float_as_uint(As[buf][(r0 + 8) * ASTR + 8 * s + tig]);
            a[2] = __float_as_uint(As[buf][r0 * ASTR + 8 * s + 4 + tig]);
            a[3] = __float_as_uint(As[buf][(r0 + 8) * ASTR + 8 * s + 4 + tig]);
            #pragma unroll
            for (int nt = 0; nt < 4; nt++) {
                const int c = warpCol + nt * 8 + g;
                b[nt][0] = __float_as_uint(Bs[buf][(8 * s + tig) * BSTR + c]);
                b[nt][1] = __float_as_uint(Bs[buf][(8 * s + 4 + tig) * BSTR + c]);
            }
            #pragma unroll
            for (int nt = 0; nt < 4; nt++) mma_tf32(acc[nt], a, b[nt]);
        }
        __syncthreads();
    }

    #pragma unroll
    for (int nt = 0; nt < 4; nt++) {
        const int row0 = bm + warpRow + g;
        const int col  = bn + warpCol + nt * 8 + 2 * tig;
        float b0 = 0.f, b1 = 0.f;
        if (bias) { b0 = bias[col]; b1 = bias[col + 1]; }
        float2 o0 = make_float2(acc[nt][0] + b0, acc[nt][1] + b1);
        float2 o1 = make_float2(acc[nt][2] + b0, acc[nt][3] + b1);
        if (res) {
            const float2 r0 = *(const float2*)&res[(size_t)row0 * N + col];
            const float2 r1 = *(const float2*)&res[(size_t)(row0 + 8) * N + col];
            o0.x += r0.x; o0.y += r0.y;
            o1.x += r1.x; o1.y += r1.y;
        }
        *(float2*)&C[(size_t)row0 * N + col]       = o0;
        *(float2*)&C[(size_t)(row0 + 8) * N + col] = o1;
    }
}

// ---------------- fused gate GEMM: silu(A@W1) * (A@W2), 32x64x32 -------------
__global__ __launch_bounds__(256) void gemm_gate_k(
    const float* __restrict__ A, const float* __restrict__ W1, const float* __restrict__ W2,
    float* __restrict__ C, int N, int K) {

    __shared__ float As [2][32 * ASTR];
    __shared__ float B1s[2][32 * BSTR];
    __shared__ float B2s[2][32 * BSTR];

    const int tid  = threadIdx.x;
    const int warp = tid >> 5;
    const int lane = tid & 31;
    const int g    = lane >> 2;
    const int tig  = lane & 3;
    const int warpRow = (warp & 1) * 16;   // 2 warp-rows
    const int warpCol = (warp >> 1) * 16;  // 4 warp-cols, 16 wide
    const int bm = blockIdx.y * 32;
    const int bn = blockIdx.x * 64;

    float acc1[2][4], acc2[2][4];
    #pragma unroll
    for (int nt = 0; nt < 2; nt++)
        #pragma unroll
        for (int i = 0; i < 4; i++) { acc1[nt][i] = 0.f; acc2[nt][i] = 0.f; }

    const int nkt = K >> 5;

    auto load_tile = [&](int buf, int k0) {
        {                                      // A: 256 chunks
            const int row = tid >> 3, kc = (tid & 7) * 4;
            cp_async16(&As[buf][row * ASTR + kc], &A[(size_t)(bm + row) * K + k0 + kc]);
        }
        #pragma unroll
        for (int j = 0; j < 2; j++) {          // each B: 512 chunks
            const int c = tid + 256 * j;
            const int row = c >> 4, nc = (c & 15) * 4;
            const size_t off = (size_t)(k0 + row) * N + bn + nc;
            cp_async16(&B1s[buf][row * BSTR + nc], &W1[off]);
            cp_async16(&B2s[buf][row * BSTR + nc], &W2[off]);
        }
        cp_commit();
    };

    load_tile(0, 0);

    for (int kt = 0; kt < nkt; kt++) {
        const int buf = kt & 1;
        if (kt + 1 < nkt) load_tile(buf ^ 1, (kt + 1) * 32);
        if (kt + 1 < nkt) asm volatile("cp.async.wait_group 1;");
        else              asm volatile("cp.async.wait_group 0;");
        __syncthreads();

        #pragma unroll
        for (int s = 0; s < 4; s++) {
            uint32_t a[4], b1[2][2], b2[2][2];
            const int r0 = warpRow + g;
            a[0] = __float_as_uint(As[buf][r0 * ASTR + 8 * s + tig]);
            a[1] = __float_as_uint(As[buf][(r0 + 8) * ASTR + 8 * s + tig]);
            a[2] = __float_as_uint(As[buf][r0 * ASTR + 8 * s + 4 + tig]);
            a[3] = __float_as_uint(As[buf][(r0 + 8) * ASTR + 8 * s + 4 + tig]);
            #pragma unroll
            for (int nt = 0; nt < 2; nt++) {
                const int c = warpCol + nt * 8 + g;
                b1[nt][0] = __float_as_uint(B1s[buf][(8 * s + tig) * BSTR + c]);
                b1[nt][1] = __float_as_uint(B1s[buf][(8 * s + 4 + tig) * BSTR + c]);
                b2[nt][0] = __float_as_uint(B2s[buf][(8 * s + tig) * BSTR + c]);
                b2[nt][1] = __float_as_uint(B2s[buf][(8 * s + 4 + tig) * BSTR + c]);
            }
            #pragma unroll
            for (int nt = 0; nt < 2; nt++) {
                mma_tf32(acc1[nt], a, b1[nt]);
                mma_tf32(acc2[nt], a, b2[nt]);
            }
        }
        __syncthreads();
    }

    #pragma unroll
    for (int nt = 0; nt < 2; nt++) {
        const int row0 = bm + warpRow + g;
        const int col  = bn + warpCol + nt * 8 + 2 * tig;
        #pragma unroll
        for (int half = 0; half < 2; half++) {
            const int row = row0 + half * 8;
            const float a0 = acc1[nt][half * 2 + 0];
            const float a1 = acc1[nt][half * 2 + 1];
            float2 o;
            o.x = a0 / (1.f + __expf(-a0)) * acc2[nt][half * 2 + 0];
            o.y = a1 / (1.f + __expf(-a1)) * acc2[nt][half * 2 + 1];
            *(float2*)&C[(size_t)row * N + col] = o;
        }
    }
}

// ---------------- NA3D attention v2: smem-tiled ------------------------------
// Block = one (4x4 spatial tile, 1 t-slice) x one head. 512 threads = 16 warps,
// warp = one token. Union neighborhood K (then V) staged in 40KB smem.
__global__ __launch_bounds__(512) void na3d_k(
    const float* __restrict__ q, const float* __restrict__ k,
    const float* __restrict__ v, float* __restrict__ out) {

    __shared__ float sm[320 * 32];     // 5 x 8 x 8 tokens x 32 channels
    __shared__ int   nbase[128];       // packed: slotbase | (mt << 16)

    const int tile = blockIdx.x;       // 0..127 : t(8) x hh(4) x ww(4)
    const int head = blockIdx.y;
    const int t  = tile >> 4;
    const int hh = (tile >> 2) & 3;
    const int ww = tile & 3;
    const int tile_h0 = hh * 4, tile_w0 = ww * 4;
    const int h_base = min(max(tile_h0 - 2, 0), 8);
    const int w_base = min(max(tile_w0 - 2, 0), 8);

    const int tid  = threadIdx.x;
    const int warp = tid >> 5;
    const int lane = tid & 31;
    const int g    = lane >> 3;        // neighbor group 0..3
    const int sub  = lane & 7;         // channel sub 0..7 (float4 each)

    if (tid < 128) {
        const int m = tid;
        int val;
        if (m < NNBR) {
            const int mt = m / 25;
            const int mh = (m / 5) % 5;
            const int mw = m % 5;
            val = (mt * 64 + mh * 8 + mw) | (mt << 16);
        } else {
            val = (-8) << 16;          // mt = -8 => always invalid; base = 0
        }
        nbase[tid] = val;
    }

    // this warp's token
    const int h = tile_h0 + (warp >> 2);
    const int w = tile_w0 + (warp & 3);
    const int token = (t * 16 + h) * 16 + w;
    const int hoff = min(max(h - 2, 0), 11) - h_base;
    const int woff = min(max(w - 2, 0), 11) - w_base;
    const int sbase = hoff * 8 + woff;

    // ---- stage K ----
    #pragma unroll
    for (int j = 0; j < 5; j++) {
        const int c = tid + 512 * j;                 // 0..2559 float4 chunks
        const int slot = c >> 3, s8 = c & 7;
        const int tl = slot >> 6, rem = slot & 63;
        const int tn = max(t - 4 + tl, 0);
        const int hn = h_base + (rem >> 3), wn = w_base + (rem & 7);
        const float4 kv = *(const float4*)&k[(size_t)((tn * 16 + hn) * 16 + wn) * DMODEL + head * DHEAD + s8 * 4];
        *(float4*)&sm[slot * 32 + s8 * 4] = kv;
    }
    const float4 q4 = *(const float4*)&q[(size_t)token * DMODEL + head * DHEAD + sub * 4];
    __syncthreads();

    // ---- logits: 4 neighbors/iter (one per 8-lane group) ----
    float lg[32];
    const float scale = 0.17677669529663687f;        // 1/sqrt(32)
    #pragma unroll
    for (int i = 0; i < 32; i++) {
        const int m   = i * 4 + g;                   // <= 127, table padded
        const int val = nbase[m];
        const int slot = (val & 0xFFFF) + sbase;
        const int mt   = val >> 16;
        const float4 kv = *(const float4*)&sm[slot * 32 + sub * 4];
        float d = q4.x * kv.x + q4.y * kv.y + q4.z * kv.z + q4.w * kv.w;
        d += __shfl_xor_sync(0xffffffffu, d, 1);
        d += __shfl_xor_sync(0xffffffffu, d, 2);
        d += __shfl_xor_sync(0xffffffffu, d, 4);
        lg[i] = (t - 4 + mt >= 0) ? d * scale : -INFINITY;
    }

    // ---- softmax over 125 (each m replicated across its 8-lane group) ----
    float mx = -INFINITY;
    #pragma unroll
    for (int i = 0; i < 32; i++) mx = fmaxf(mx, lg[i]);
    #pragma unroll
    for (int o = 16; o; o >>= 1) mx = fmaxf(mx, __shfl_xor_sync(0xffffffffu, mx, o));
    float sum = 0.f;
    #pragma unroll
    for (int i = 0; i < 32; i++) { lg[i] = __expf(lg[i] - mx); sum += lg[i]; }
    sum += __shfl_xor_sync(0xffffffffu, sum, 8);
    sum += __shfl_xor_sync(0xffffffffu, sum, 16);
    const float inv = 1.f / sum;

    // ---- stage V (reuse buffer) ----
    __syncthreads();
    #pragma unroll
    for (int j = 0; j < 5; j++) {
        const int c = tid + 512 * j;
        const int slot = c >> 3, s8 = c & 7;
        const int tl = slot >> 6, rem = slot & 63;
        const int tn = max(t - 4 + tl, 0);
        const int hn = h_base + (rem >> 3), wn = w_base + (rem & 7);
        const float4 vv = *(const float4*)&v[(size_t)((tn * 16 + hn) * 16 + wn) * DMODEL + head * DHEAD + s8 * 4];
        *(float4*)&sm[slot * 32 + s8 * 4] = vv;
    }
    __syncthreads();

    // ---- weighted V accumulation ----
    float4 acc = make_float4(0.f, 0.f, 0.f, 0.f);
    #pragma unroll
    for (int i = 0; i < 32; i++) {
        const int m    = i * 4 + g;
        const int slot = (nbase[m] & 0xFFFF) + sbase;
        const float4 vv = *(const float4*)&sm[slot * 32 + sub * 4];
        const float p = lg[i];                       // 0 for invalid entries
        acc.x = fmaf(p, vv.x, acc.x);
        acc.y = fmaf(p, vv.y, acc.y);
        acc.z = fmaf(p, vv.z, acc.z);
        acc.w = fmaf(p, vv.w, acc.w);
    }
    #pragma unroll
    for (int o = 8; o <= 16; o <<= 1) {
        acc.x += __shfl_xor_sync(0xffffffffu, acc.x, o);
        acc.y += __shfl_xor_sync(0xffffffffu, acc.y, o);
        acc.z += __shfl_xor_sync(0xffffffffu, acc.z, o);
        acc.w += __shfl_xor_sync(0xffffffffu, acc.w, o);
    }
    if (g == 0) {
        float4 o4 = make_float4(acc.x * inv, acc.y * inv, acc.z * inv, acc.w * inv);
        *(float4*)&out[(size_t)token * DMODEL + head * DHEAD + sub * 4] = o4;
    }
}

// ---------------- launch ------------------------------------------------------
extern "C" void kernel_launch(void* const* d_in, const int* in_sizes, int n_in,
                              void* d_out, int out_size) {
    const float* x   = (const float*)d_in[0];
    const float* n1w = (const float*)d_in[1];
    const float* n2w = (const float*)d_in[2];
    const float* wq  = (const float*)d_in[3];
    const float* bq  = (const float*)d_in[4];
    const float* wk  = (const float*)d_in[5];
    const float* bk  = (const float*)d_in[6];
    const float* wv  = (const float*)d_in[7];
    const float* bv  = (const float*)d_in[8];
    const float* wo  = (const float*)d_in[9];
    const float* bo  = (const float*)d_in[10];
    const float* w1  = (const float*)d_in[11];
    const float* w2  = (const float*)d_in[12];
    const float* w3  = (const float*)d_in[13];
    float* out = (float*)d_out;

    float *p_n1, *p_q, *p_k, *p_v, *p_at, *p_h, *p_y, *p_fa;
    cudaGetSymbolAddress((void**)&p_n1, g_n1);
    cudaGetSymbolAddress((void**)&p_q,  g_q);
    cudaGetSymbolAddress((void**)&p_k,  g_k);
    cudaGetSymbolAddress((void**)&p_v,  g_v);
    cudaGetSymbolAddress((void**)&p_at, g_at);
    cudaGetSymbolAddress((void**)&p_h,  g_h);
    cudaGetSymbolAddress((void**)&p_y,  g_y);
    cudaGetSymbolAddress((void**)&p_fa, g_fa);

    const dim3 blk(256);

    // 1) n1 = rmsnorm(x, norm1_w)
    rmsnorm_k<<<NTOK, DMODEL>>>(x, n1w, p_n1);

    // 2) q,k,v = n1 @ {wq,wk,wv} + bias   (fused via grid.z)
    gemm_tf32_k<<<dim3(DMODEL / 64, NTOK / 64, 3), blk>>>(
        p_n1, wq, wk, wv, bq, bk, bv, nullptr, p_q, p_k, p_v, DMODEL, DMODEL);

    // 3) neighborhood attention (smem-tiled)
    na3d_k<<<dim3(128, NHEAD), 512>>>(p_q, p_k, p_v, p_at);

    // 4) h = x + attn @ wo + bo
    gemm_tf32_k<<<dim3(DMODEL / 64, NTOK / 64, 1), blk>>>(
        p_at, wo, nullptr, nullptr, bo, nullptr, nullptr, x, p_h, nullptr, nullptr,
        DMODEL, DMODEL);

    // 5) y = rmsnorm(h, norm2_w)
    rmsnorm_k<<<NTOK, DMODEL>>>(p_h, n2w, p_y);

    // 6) fa = silu(y@w1) * (y@w2)   (fused dual-B GEMM)
    gemm_gate_k<<<dim3(DFF / 64, NTOK / 32), blk>>>(p_y, w1, w2, p_fa, DFF, DMODEL);

    // 7) out = h + fa @ w3
    gemm_tf32_k<<<dim3(DMODEL / 64, NTOK / 64, 1), blk>>>(
        p_fa, w3, nullptr, nullptr, nullptr, nullptr, nullptr, p_h, out, nullptr, nullptr,
        DMODEL, DFF);
}

// round 4
// speedup vs baseline: 2.7199x; 1.0328x over previous
#include <cuda_runtime.h>
#include <math.h>
#include <stdint.h>

#define NTOK   2048
#define DMODEL 256
#define DFF    1024
#define NHEAD  8
#define DHEAD  32
#define KWIN   5
#define NNBR   125   // 5*5*5

// ---------------- scratch (device globals; no allocations allowed) ----------
__device__ float g_q [NTOK * DMODEL];
__device__ float g_k [NTOK * DMODEL];
__device__ float g_v [NTOK * DMODEL];
__device__ float g_at[NTOK * DMODEL];
__device__ float g_h [NTOK * DMODEL];
__device__ float g_fa[NTOK * DFF];
__device__ float g_rs1[NTOK];
__device__ float g_rs2[NTOK];

// ---------------- helpers ----------------------------------------------------
__device__ __forceinline__ void mma_tf32(float d[4], const uint32_t a[4], const uint32_t b[2]) {
    asm volatile(
        "mma.sync.aligned.m16n8k8.row.col.f32.tf32.tf32.f32 "
        "{%0,%1,%2,%3},{%4,%5,%6,%7},{%8,%9},{%0,%1,%2,%3};"
        : "+f"(d[0]), "+f"(d[1]), "+f"(d[2]), "+f"(d[3])
        : "r"(a[0]), "r"(a[1]), "r"(a[2]), "r"(a[3]), "r"(b[0]), "r"(b[1]));
}

__device__ __forceinline__ void cp_async16(void* smem_dst, const void* gsrc) {
    uint32_t s = (uint32_t)__cvta_generic_to_shared(smem_dst);
    asm volatile("cp.async.cg.shared.global [%0], [%1], 16;" :: "r"(s), "l"(gsrc));
}
__device__ __forceinline__ void cp_commit() { asm volatile("cp.async.commit_group;"); }

#define ASTR 36   // A smem stride (words per m-row)
#define BSTR 68   // B smem stride (words per k-row)

// ---------------- RMS scale: one warp per token ------------------------------
// rscale[tok] = rsqrt(mean(x[tok,:]^2) + eps)
__global__ __launch_bounds__(256) void rms_scale_k(const float* __restrict__ x,
                                                   float* __restrict__ rscale) {
    const int warp = threadIdx.x >> 5;
    const int lane = threadIdx.x & 31;
    const int token = blockIdx.x * 8 + warp;
    const float4 a = *(const float4*)&x[(size_t)token * DMODEL + lane * 4];
    const float4 b = *(const float4*)&x[(size_t)token * DMODEL + 128 + lane * 4];
    float s = a.x * a.x + a.y * a.y + a.z * a.z + a.w * a.w
            + b.x * b.x + b.y * b.y + b.z * b.z + b.w * b.w;
    #pragma unroll
    for (int o = 16; o; o >>= 1) s += __shfl_xor_sync(0xffffffffu, s, o);
    if (lane == 0) rscale[token] = rsqrtf(s * (1.0f / DMODEL) + 1e-6f);
}

// ---------------- TF32 GEMM v3: 32x64x32 tiles, 128 thr, cp.async dbl-buf ----
// Optional fused RMSNorm on A: A_eff[m,k] = A[m,k] * rs[m] * nw[k].
// blockIdx.z selects among up to 3 (B, bias, C) triples (QKV fusion).
__global__ __launch_bounds__(128) void gemm_tf32_k(
    const float* __restrict__ A,
    const float* __restrict__ rs, const float* __restrict__ nw,
    const float* __restrict__ B0, const float* __restrict__ B1, const float* __restrict__ B2,
    const float* __restrict__ bias0, const float* __restrict__ bias1, const float* __restrict__ bias2,
    const float* __restrict__ res,
    float* __restrict__ C0, float* __restrict__ C1, float* __restrict__ C2,
    int N, int K) {

    const int z = blockIdx.z;
    const float* B    = (z == 0) ? B0    : (z == 1) ? B1    : B2;
    const float* bias = (z == 0) ? bias0 : (z == 1) ? bias1 : bias2;
    float*       C    = (z == 0) ? C0    : (z == 1) ? C1    : C2;

    __shared__ float As[2][32 * ASTR];
    __shared__ float Bs[2][32 * BSTR];

    const int tid  = threadIdx.x;
    const int warp = tid >> 5;
    const int lane = tid & 31;
    const int g    = lane >> 2;
    const int tig  = lane & 3;
    const int warpRow = (warp & 1) * 16;   // 2 warp-rows
    const int warpCol = (warp >> 1) * 32;  // 2 warp-cols
    const int bm = blockIdx.y * 32;
    const int bn = blockIdx.x * 64;

    float acc[4][4];
    #pragma unroll
    for (int nt = 0; nt < 4; nt++)
        #pragma unroll
        for (int i = 0; i < 4; i++) acc[nt][i] = 0.f;

    const int nkt = K >> 5;

    auto load_tile = [&](int buf, int k0) {
        if (rs) {
            #pragma unroll
            for (int j = 0; j < 2; j++) {      // A: 256 float4 chunks, scaled
                const int c = tid + 128 * j;
                const int row = c >> 3, kc = (c & 7) * 4;
                const float4 xv = *(const float4*)&A[(size_t)(bm + row) * K + k0 + kc];
                const float4 wv = *(const float4*)&nw[k0 + kc];
                const float sc = rs[bm + row];
                float4 r;
                r.x = xv.x * sc * wv.x; r.y = xv.y * sc * wv.y;
                r.z = xv.z * sc * wv.z; r.w = xv.w * sc * wv.w;
                *(float4*)&As[buf][row * ASTR + kc] = r;
            }
        } else {
            #pragma unroll
            for (int j = 0; j < 2; j++) {
                const int c = tid + 128 * j;
                const int row = c >> 3, kc = (c & 7) * 4;
                cp_async16(&As[buf][row * ASTR + kc], &A[(size_t)(bm + row) * K + k0 + kc]);
            }
        }
        #pragma unroll
        for (int j = 0; j < 4; j++) {          // B: 512 float4 chunks
            const int c = tid + 128 * j;
            const int row = c >> 4, nc = (c & 15) * 4;
            cp_async16(&Bs[buf][row * BSTR + nc], &B[(size_t)(k0 + row) * N + bn + nc]);
        }
        cp_commit();
    };

    load_tile(0, 0);

    for (int kt = 0; kt < nkt; kt++) {
        const int buf = kt & 1;
        if (kt + 1 < nkt) load_tile(buf ^ 1, (kt + 1) * 32);
        if (kt + 1 < nkt) asm volatile("cp.async.wait_group 1;");
        else              asm volatile("cp.async.wait_group 0;");
        __syncthreads();

        #pragma unroll
        for (int s = 0; s < 4; s++) {
            uint32_t a[4], b[4][2];
            const int r0 = warpRow + g;
            a[0] = __float_as_uint(As[buf][r0 * ASTR + 8 * s + tig]);
            a[1] = __float_as_uint(As[buf][(r0 + 8) * ASTR + 8 * s + tig]);
            a[2] = __float_as_uint(As[buf][r0 * ASTR + 8 * s + 4 + tig]);
            a[3] = __float_as_uint(As[buf][(r0 + 8) * ASTR + 8 * s + 4 + tig]);
            #pragma unroll
            for (int nt = 0; nt < 4; nt++) {
                const int c = warpCol + nt * 8 + g;
                b[nt][0] = __float_as_uint(Bs[buf][(8 * s + tig) * BSTR + c]);
                b[nt][1] = __float_as_uint(Bs[buf][(8 * s + 4 + tig) * BSTR + c]);
            }
            #pragma unroll
            for (int nt = 0; nt < 4; nt++) mma_tf32(acc[nt], a, b[nt]);
        }
        __syncthreads();
    }

    #pragma unroll
    for (int nt = 0; nt < 4; nt++) {
        const int row0 = bm + warpRow + g;
        const int col  = bn + warpCol + nt * 8 + 2 * tig;
        float b0 = 0.f, b1 = 0.f;
        if (bias) { b0 = bias[col]; b1 = bias[col + 1]; }
        float2 o0 = make_float2(acc[nt][0] + b0, acc[nt][1] + b1);
        float2 o1 = make_float2(acc[nt][2] + b0, acc[nt][3] + b1);
        if (res) {
            const float2 r0 = *(const float2*)&res[(size_t)row0 * N + col];
            const float2 r1 = *(const float2*)&res[(size_t)(row0 + 8) * N + col];
            o0.x += r0.x; o0.y += r0.y;
            o1.x += r1.x; o1.y += r1.y;
        }
        *(float2*)&C[(size_t)row0 * N + col]       = o0;
        *(float2*)&C[(size_t)(row0 + 8) * N + col] = o1;
    }
}

// ---------------- fused gate GEMM: silu(A'@W1) * (A'@W2), A'=rmsnorm(A) ------
__global__ __launch_bounds__(128) void gemm_gate_k(
    const float* __restrict__ A,
    const float* __restrict__ rs, const float* __restrict__ nw,
    const float* __restrict__ W1, const float* __restrict__ W2,
    float* __restrict__ C, int N, int K) {

    __shared__ float As [2][32 * ASTR];
    __shared__ float B1s[2][32 * BSTR];
    __shared__ float B2s[2][32 * BSTR];

    const int tid  = threadIdx.x;
    const int warp = tid >> 5;
    const int lane = tid & 31;
    const int g    = lane >> 2;
    const int tig  = lane & 3;
    const int warpRow = (warp & 1) * 16;
    const int warpCol = (warp >> 1) * 32;
    const int bm = blockIdx.y * 32;
    const int bn = blockIdx.x * 64;

    float acc1[4][4], acc2[4][4];
    #pragma unroll
    for (int nt = 0; nt < 4; nt++)
        #pragma unroll
        for (int i = 0; i < 4; i++) { acc1[nt][i] = 0.f; acc2[nt][i] = 0.f; }

    const int nkt = K >> 5;

    auto load_tile = [&](int buf, int k0) {
        #pragma unroll
        for (int j = 0; j < 2; j++) {          // A scaled
            const int c = tid + 128 * j;
            const int row = c >> 3, kc = (c & 7) * 4;
            const float4 xv = *(const float4*)&A[(size_t)(bm + row) * K + k0 + kc];
            const float4 wv = *(const float4*)&nw[k0 + kc];
            const float sc = rs[bm + row];
            float4 r;
            r.x = xv.x * sc * wv.x; r.y = xv.y * sc * wv.y;
            r.z = xv.z * sc * wv.z; r.w = xv.w * sc * wv.w;
            *(float4*)&As[buf][row * ASTR + kc] = r;
        }
        #pragma unroll
        for (int j = 0; j < 4; j++) {
            const int c = tid + 128 * j;
            const int row = c >> 4, nc = (c & 15) * 4;
            const size_t off = (size_t)(k0 + row) * N + bn + nc;
            cp_async16(&B1s[buf][row * BSTR + nc], &W1[off]);
            cp_async16(&B2s[buf][row * BSTR + nc], &W2[off]);
        }
        cp_commit();
    };

    load_tile(0, 0);

    for (int kt = 0; kt < nkt; kt++) {
        const int buf = kt & 1;
        if (kt + 1 < nkt) load_tile(buf ^ 1, (kt + 1) * 32);
        if (kt + 1 < nkt) asm volatile("cp.async.wait_group 1;");
        else              asm volatile("cp.async.wait_group 0;");
        __syncthreads();

        #pragma unroll
        for (int s = 0; s < 4; s++) {
            uint32_t a[4], b1[4][2], b2[4][2];
            const int r0 = warpRow + g;
            a[0] = __float_as_uint(As[buf][r0 * ASTR + 8 * s + tig]);
            a[1] = __float_as_uint(As[buf][(r0 + 8) * ASTR + 8 * s + tig]);
            a[2] = __float_as_uint(As[buf][r0 * ASTR + 8 * s + 4 + tig]);
            a[3] = __float_as_uint(As[buf][(r0 + 8) * ASTR + 8 * s + 4 + tig]);
            #pragma unroll
            for (int nt = 0; nt < 4; nt++) {
                const int c = warpCol + nt * 8 + g;
                b1[nt][0] = __float_as_uint(B1s[buf][(8 * s + tig) * BSTR + c]);
                b1[nt][1] = __float_as_uint(B1s[buf][(8 * s + 4 + tig) * BSTR + c]);
                b2[nt][0] = __float_as_uint(B2s[buf][(8 * s + tig) * BSTR + c]);
                b2[nt][1] = __float_as_uint(B2s[buf][(8 * s + 4 + tig) * BSTR + c]);
            }
            #pragma unroll
            for (int nt = 0; nt < 4; nt++) {
                mma_tf32(acc1[nt], a, b1[nt]);
                mma_tf32(acc2[nt], a, b2[nt]);
            }
        }
        __syncthreads();
    }

    #pragma unroll
    for (int nt = 0; nt < 4; nt++) {
        const int row0 = bm + warpRow + g;
        const int col  = bn + warpCol + nt * 8 + 2 * tig;
        #pragma unroll
        for (int half = 0; half < 2; half++) {
            const int row = row0 + half * 8;
            const float a0 = acc1[nt][half * 2 + 0];
            const float a1 = acc1[nt][half * 2 + 1];
            float2 o;
            o.x = a0 / (1.f + __expf(-a0)) * acc2[nt][half * 2 + 0];
            o.y = a1 / (1.f + __expf(-a1)) * acc2[nt][half * 2 + 1];
            *(float2*)&C[(size_t)row * N + col] = o;
        }
    }
}

// ---------------- NA3D attention: smem-tiled ---------------------------------
__global__ __launch_bounds__(512) void na3d_k(
    const float* __restrict__ q, const float* __restrict__ k,
    const float* __restrict__ v, float* __restrict__ out) {

    __shared__ float sm[320 * 32];     // 5 x 8 x 8 tokens x 32 channels
    __shared__ int   nbase[128];       // packed: slotbase | (mt << 16)

    const int tile = blockIdx.x;       // 0..127 : t(8) x hh(4) x ww(4)
    const int head = blockIdx.y;
    const int t  = tile >> 4;
    const int hh = (tile >> 2) & 3;
    const int ww = tile & 3;
    const int tile_h0 = hh * 4, tile_w0 = ww * 4;
    const int h_base = min(max(tile_h0 - 2, 0), 8);
    const int w_base = min(max(tile_w0 - 2, 0), 8);

    const int tid  = threadIdx.x;
    const int warp = tid >> 5;
    const int lane = tid & 31;
    const int g    = lane >> 3;
    const int sub  = lane & 7;

    if (tid < 128) {
        const int m = tid;
        int val;
        if (m < NNBR) {
            const int mt = m / 25;
            const int mh = (m / 5) % 5;
            const int mw = m % 5;
            val = (mt * 64 + mh * 8 + mw) | (mt << 16);
        } else {
            val = (-8) << 16;
        }
        nbase[tid] = val;
    }

    const int h = tile_h0 + (warp >> 2);
    const int w = tile_w0 + (warp & 3);
    const int token = (t * 16 + h) * 16 + w;
    const int hoff = min(max(h - 2, 0), 11) - h_base;
    const int woff = min(max(w - 2, 0), 11) - w_base;
    const int sbase = hoff * 8 + woff;

    #pragma unroll
    for (int j = 0; j < 5; j++) {
        const int c = tid + 512 * j;
        const int slot = c >> 3, s8 = c & 7;
        const int tl = slot >> 6, rem = slot & 63;
        const int tn = max(t - 4 + tl, 0);
        const int hn = h_base + (rem >> 3), wn = w_base + (rem & 7);
        const float4 kv = *(const float4*)&k[(size_t)((tn * 16 + hn) * 16 + wn) * DMODEL + head * DHEAD + s8 * 4];
        *(float4*)&sm[slot * 32 + s8 * 4] = kv;
    }
    const float4 q4 = *(const float4*)&q[(size_t)token * DMODEL + head * DHEAD + sub * 4];
    __syncthreads();

    float lg[32];
    const float scale = 0.17677669529663687f;
    #pragma unroll
    for (int i = 0; i < 32; i++) {
        const int m   = i * 4 + g;
        const int val = nbase[m];
        const int slot = (val & 0xFFFF) + sbase;
        const int mt   = val >> 16;
        const float4 kv = *(const float4*)&sm[slot * 32 + sub * 4];
        float d = q4.x * kv.x + q4.y * kv.y + q4.z * kv.z + q4.w * kv.w;
        d += __shfl_xor_sync(0xffffffffu, d, 1);
        d += __shfl_xor_sync(0xffffffffu, d, 2);
        d += __shfl_xor_sync(0xffffffffu, d, 4);
        lg[i] = (t - 4 + mt >= 0) ? d * scale : -INFINITY;
    }

    float mx = -INFINITY;
    #pragma unroll
    for (int i = 0; i < 32; i++) mx = fmaxf(mx, lg[i]);
    #pragma unroll
    for (int o = 16; o; o >>= 1) mx = fmaxf(mx, __shfl_xor_sync(0xffffffffu, mx, o));
    float sum = 0.f;
    #pragma unroll
    for (int i = 0; i < 32; i++) { lg[i] = __expf(lg[i] - mx); sum += lg[i]; }
    sum += __shfl_xor_sync(0xffffffffu, sum, 8);
    sum += __shfl_xor_sync(0xffffffffu, sum, 16);
    const float inv = 1.f / sum;

    __syncthreads();
    #pragma unroll
    for (int j = 0; j < 5; j++) {
        const int c = tid + 512 * j;
        const int slot = c >> 3, s8 = c & 7;
        const int tl = slot >> 6, rem = slot & 63;
        const int tn = max(t - 4 + tl, 0);
        const int hn = h_base + (rem >> 3), wn = w_base + (rem & 7);
        const float4 vv = *(const float4*)&v[(size_t)((tn * 16 + hn) * 16 + wn) * DMODEL + head * DHEAD + s8 * 4];
        *(float4*)&sm[slot * 32 + s8 * 4] = vv;
    }
    __syncthreads();

    float4 acc = make_float4(0.f, 0.f, 0.f, 0.f);
    #pragma unroll
    for (int i = 0; i < 32; i++) {
        const int m    = i * 4 + g;
        const int slot = (nbase[m] & 0xFFFF) + sbase;
        const float4 vv = *(const float4*)&sm[slot * 32 + sub * 4];
        const float p = lg[i];
        acc.x = fmaf(p, vv.x, acc.x);
        acc.y = fmaf(p, vv.y, acc.y);
        acc.z = fmaf(p, vv.z, acc.z);
        acc.w = fmaf(p, vv.w, acc.w);
    }
    #pragma unroll
    for (int o = 8; o <= 16; o <<= 1) {
        acc.x += __shfl_xor_sync(0xffffffffu, acc.x, o);
        acc.y += __shfl_xor_sync(0xffffffffu, acc.y, o);
        acc.z += __shfl_xor_sync(0xffffffffu, acc.z, o);
        acc.w += __shfl_xor_sync(0xffffffffu, acc.w, o);
    }
    if (g == 0) {
        float4 o4 = make_float4(acc.x * inv, acc.y * inv, acc.z * inv, acc.w * inv);
        *(float4*)&out[(size_t)token * DMODEL + head * DHEAD + sub * 4] = o4;
    }
}

// ---------------- launch ------------------------------------------------------
extern "C" void kernel_launch(void* const* d_in, const int* in_sizes, int n_in,
                              void* d_out, int out_size) {
    const float* x   = (const float*)d_in[0];
    const float* n1w = (const float*)d_in[1];
    const float* n2w = (const float*)d_in[2];
    const float* wq  = (const float*)d_in[3];
    const float* bq  = (const float*)d_in[4];
    const float* wk  = (const float*)d_in[5];
    const float* bk  = (const float*)d_in[6];
    const float* wv  = (const float*)d_in[7];
    const float* bv  = (const float*)d_in[8];
    const float* wo  = (const float*)d_in[9];
    const float* bo  = (const float*)d_in[10];
    const float* w1  = (const float*)d_in[11];
    const float* w2  = (const float*)d_in[12];
    const float* w3  = (const float*)d_in[13];
    float* out = (float*)d_out;

    float *p_q, *p_k, *p_v, *p_at, *p_h, *p_fa, *p_rs1, *p_rs2;
    cudaGetSymbolAddress((void**)&p_q,  g_q);
    cudaGetSymbolAddress((void**)&p_k,  g_k);
    cudaGetSymbolAddress((void**)&p_v,  g_v);
    cudaGetSymbolAddress((void**)&p_at, g_at);
    cudaGetSymbolAddress((void**)&p_h,  g_h);
    cudaGetSymbolAddress((void**)&p_fa, g_fa);
    cudaGetSymbolAddress((void**)&p_rs1, g_rs1);
    cudaGetSymbolAddress((void**)&p_rs2, g_rs2);

    const dim3 blk(128);

    // 1) rscale1 = rms scale of x
    rms_scale_k<<<NTOK / 8, 256>>>(x, p_rs1);

    // 2) q,k,v = rmsnorm(x) @ {wq,wk,wv} + bias   (norm fused into A-load)
    gemm_tf32_k<<<dim3(DMODEL / 64, NTOK / 32, 3), blk>>>(
        x, p_rs1, n1w, wq, wk, wv, bq, bk, bv, nullptr, p_q, p_k, p_v, DMODEL, DMODEL);

    // 3) neighborhood attention
    na3d_k<<<dim3(128, NHEAD), 512>>>(p_q, p_k, p_v, p_at);

    // 4) h = x + attn @ wo + bo
    gemm_tf32_k<<<dim3(DMODEL / 64, NTOK / 32, 1), blk>>>(
        p_at, nullptr, nullptr, wo, nullptr, nullptr, bo, nullptr, nullptr, x,
        p_h, nullptr, nullptr, DMODEL, DMODEL);

    // 5) rscale2 = rms scale of h
    rms_scale_k<<<NTOK / 8, 256>>>(p_h, p_rs2);

    // 6) fa = silu(rmsnorm(h)@w1) * (rmsnorm(h)@w2)
    gemm_gate_k<<<dim3(DFF / 64, NTOK / 32), blk>>>(p_h, p_rs2, n2w, w1, w2, p_fa, DFF, DMODEL);

    // 7) out = h + fa @ w3
    gemm_tf32_k<<<dim3(DMODEL / 64, NTOK / 32, 1), blk>>>(
        p_fa, nullptr, nullptr, w3, nullptr, nullptr, nullptr, nullptr, nullptr, p_h,
        out, nullptr, nullptr, DMODEL, DFF);
}